// round 7
// baseline (speedup 1.0000x reference)
#include <cuda_runtime.h>

// Gated DeltaNet single step, reduced form:
//   out[v] = g*(q . S[:,v]) + (q . k)*beta*(v[v] - g*(k . S[:,v]))
// One warp per (b,h), 8 warps/CTA. Lane owns 4 columns via float4.
// state is read-once: stream with __ldcs (evict-first) to cut L2 thrash.
// Unroll 16 -> 256B outstanding per thread for deeper DRAM queues.

#define DK 128
#define DV 128
#define WARPS_PER_CTA 8

__global__ __launch_bounds__(WARPS_PER_CTA * 32)
void deltanet_step_kernel(const float* __restrict__ q,
                          const float* __restrict__ k,
                          const float* __restrict__ v,
                          const float* __restrict__ beta,
                          const float* __restrict__ gate,
                          const float* __restrict__ state,
                          float* __restrict__ out,
                          int BH) {
    const int warp = threadIdx.x >> 5;
    const int lane = threadIdx.x & 31;
    const int bh   = blockIdx.x * WARPS_PER_CTA + warp;
    if (bh >= BH) return;

    __shared__ float sq[WARPS_PER_CTA][DK];
    __shared__ float sk[WARPS_PER_CTA][DK];

    const float4 q4 = reinterpret_cast<const float4*>(q + (size_t)bh * DK)[lane];
    const float4 k4 = reinterpret_cast<const float4*>(k + (size_t)bh * DK)[lane];
    reinterpret_cast<float4*>(sq[warp])[lane] = q4;
    reinterpret_cast<float4*>(sk[warp])[lane] = k4;
    __syncwarp();

    // q . k from registers via butterfly reduce
    float qk = q4.x * k4.x + q4.y * k4.y + q4.z * k4.z + q4.w * k4.w;
    #pragma unroll
    for (int off = 16; off > 0; off >>= 1)
        qk += __shfl_xor_sync(0xFFFFFFFFu, qk, off);

    const float4* S = reinterpret_cast<const float4*>(state + (size_t)bh * (DK * DV));

    float4 qS = make_float4(0.f, 0.f, 0.f, 0.f);
    float4 kS = make_float4(0.f, 0.f, 0.f, 0.f);

    #pragma unroll 16
    for (int kk = 0; kk < DK; ++kk) {
        const float4 s = __ldcs(&S[kk * (DV / 4) + lane]);  // streaming, read-once
        const float qc = sq[warp][kk];                      // smem broadcast
        const float kc = sk[warp][kk];
        qS.x = fmaf(qc, s.x, qS.x);  kS.x = fmaf(kc, s.x, kS.x);
        qS.y = fmaf(qc, s.y, qS.y);  kS.y = fmaf(kc, s.y, kS.y);
        qS.z = fmaf(qc, s.z, qS.z);  kS.z = fmaf(kc, s.z, kS.z);
        qS.w = fmaf(qc, s.w, qS.w);  kS.w = fmaf(kc, s.w, kS.w);
    }

    const float g  = gate[bh];
    const float bt = beta[bh];
    const float bq = qk * bt;
    const float4 vv = reinterpret_cast<const float4*>(v + (size_t)bh * DV)[lane];

    float4 o;
    o.x = fmaf(g, qS.x, bq * (vv.x - g * kS.x));
    o.y = fmaf(g, qS.y, bq * (vv.y - g * kS.y));
    o.z = fmaf(g, qS.z, bq * (vv.z - g * kS.z));
    o.w = fmaf(g, qS.w, bq * (vv.w - g * kS.w));
    reinterpret_cast<float4*>(out + (size_t)bh * DV)[lane] = o;
}

extern "C" void kernel_launch(void* const* d_in, const int* in_sizes, int n_in,
                              void* d_out, int out_size) {
    const float* q     = (const float*)d_in[0];
    const float* k     = (const float*)d_in[1];
    const float* v     = (const float*)d_in[2];
    const float* beta  = (const float*)d_in[3];
    const float* gate  = (const float*)d_in[4];
    const float* state = (const float*)d_in[5];
    float* out = (float*)d_out;

    const int BH = in_sizes[3];   // beta: B*H elements
    const int grid = (BH + WARPS_PER_CTA - 1) / WARPS_PER_CTA;

    deltanet_step_kernel<<<grid, WARPS_PER_CTA * 32>>>(q, k, v, beta, gate, state, out, BH);
}

// round 8
// speedup vs baseline: 1.0658x; 1.0658x over previous
#include <cuda_runtime.h>
#include <cstdint>

// Gated DeltaNet single step:
//   out[v] = g*(q . S[:,v]) + (q . k)*beta*(v[v] - g*(k . S[:,v]))
// One CTA (128 thr) per head. Full 64KB state prefetched via 8x8KB
// cp.async.bulk (TMA path, multi-KB DRAM requests) into dynamic smem;
// per-chunk mbarriers overlap compute with the remaining loads.

#define DK 128
#define DV 128
#define NWARP 4
#define NCHUNK 8
#define CHUNK_ROWS 16                       // 16 rows * 512B = 8KB
#define CHUNK_BYTES (CHUNK_ROWS * DV * 4)
#define ROWS_PER_WARP (CHUNK_ROWS / NWARP)  // 4

__device__ __forceinline__ uint32_t smem_u32(const void* p) {
    return (uint32_t)__cvta_generic_to_shared(p);
}

__device__ __forceinline__ void mbar_wait(uint32_t mbar, uint32_t parity) {
    asm volatile(
        "{\n\t"
        ".reg .pred P;\n\t"
        "WAIT_%=:\n\t"
        "mbarrier.try_wait.parity.acquire.cta.shared::cta.b64 P, [%0], %1, 0x989680;\n\t"
        "@P bra WAIT_DONE_%=;\n\t"
        "bra WAIT_%=;\n\t"
        "WAIT_DONE_%=:\n\t"
        "}"
        :: "r"(mbar), "r"(parity) : "memory");
}

__global__ void __launch_bounds__(128, 3)
deltanet_tma_kernel(const float* __restrict__ q,
                    const float* __restrict__ k,
                    const float* __restrict__ v,
                    const float* __restrict__ beta,
                    const float* __restrict__ gate,
                    const float* __restrict__ state,
                    float* __restrict__ out) {
    extern __shared__ __align__(128) float sS[];   // NCHUNK*CHUNK_ROWS*DV = 64KB

    __shared__ float sq[DK];
    __shared__ float sk[DK];
    __shared__ float redQ[NWARP][DV];
    __shared__ float redK[NWARP][DV];
    __shared__ float wqk[NWARP];
    __shared__ __align__(8) unsigned long long mbar[NCHUNK];

    const int bh   = blockIdx.x;
    const int t    = threadIdx.x;        // 0..127
    const int warp = t >> 5;
    const int lane = t & 31;

    if (t == 0) {
        #pragma unroll
        for (int c = 0; c < NCHUNK; ++c) {
            asm volatile("mbarrier.init.shared.b64 [%0], 1;"
                         :: "r"(smem_u32(&mbar[c])) : "memory");
        }
    }

    // q,k for this head; per-warp partial of q.k
    const float qt = q[(size_t)bh * DK + t];
    const float kt = k[(size_t)bh * DK + t];
    sq[t] = qt;
    sk[t] = kt;
    float p = qt * kt;
    #pragma unroll
    for (int off = 16; off > 0; off >>= 1)
        p += __shfl_xor_sync(0xFFFFFFFFu, p, off);
    if (lane == 0) wqk[warp] = p;
    __syncthreads();   // barriers initialized + sq/sk/wqk visible

    // Thread 0 launches all 8 bulk copies (64KB total) up front.
    if (t == 0) {
        const char* gsrc = (const char*)(state + (size_t)bh * (DK * DV));
        #pragma unroll
        for (int c = 0; c < NCHUNK; ++c) {
            const uint32_t mb  = smem_u32(&mbar[c]);
            const uint32_t dst = smem_u32(sS) + c * CHUNK_BYTES;
            asm volatile("mbarrier.arrive.expect_tx.shared.b64 _, [%0], %1;"
                         :: "r"(mb), "r"((uint32_t)CHUNK_BYTES) : "memory");
            asm volatile(
                "cp.async.bulk.shared::cta.global.mbarrier::complete_tx::bytes "
                "[%0], [%1], %2, [%3];"
                :: "r"(dst), "l"(gsrc + (size_t)c * CHUNK_BYTES),
                   "r"((uint32_t)CHUNK_BYTES), "r"(mb) : "memory");
        }
    }

    const float qk = wqk[0] + wqk[1] + wqk[2] + wqk[3];

    float4 qS = make_float4(0.f, 0.f, 0.f, 0.f);
    float4 kS = make_float4(0.f, 0.f, 0.f, 0.f);

    for (int c = 0; c < NCHUNK; ++c) {
        mbar_wait(smem_u32(&mbar[c]), 0);
        const float4* Sc = reinterpret_cast<const float4*>(sS + c * CHUNK_ROWS * DV);
        #pragma unroll
        for (int i = 0; i < ROWS_PER_WARP; ++i) {
            const int r  = warp * ROWS_PER_WARP + i;   // row within chunk
            const int kk = c * CHUNK_ROWS + r;         // global row
            const float4 s = Sc[r * (DV / 4) + lane];  // conflict-free
            const float qc = sq[kk];
            const float kc = sk[kk];
            qS.x = fmaf(qc, s.x, qS.x);  kS.x = fmaf(kc, s.x, kS.x);
            qS.y = fmaf(qc, s.y, qS.y);  kS.y = fmaf(kc, s.y, kS.y);
            qS.z = fmaf(qc, s.z, qS.z);  kS.z = fmaf(kc, s.z, kS.z);
            qS.w = fmaf(qc, s.w, qS.w);  kS.w = fmaf(kc, s.w, kS.w);
        }
    }

    // Cross-warp reduction of partial qS/kS (each warp covered 1/4 of rows).
    reinterpret_cast<float4*>(&redQ[warp][0])[lane] = qS;
    reinterpret_cast<float4*>(&redK[warp][0])[lane] = kS;
    __syncthreads();

    const float qs = redQ[0][t] + redQ[1][t] + redQ[2][t] + redQ[3][t];
    const float ks = redK[0][t] + redK[1][t] + redK[2][t] + redK[3][t];

    const float g  = gate[bh];
    const float bt = beta[bh];
    const float vv = v[(size_t)bh * DV + t];

    out[(size_t)bh * DV + t] = fmaf(g, qs, (qk * bt) * (vv - g * ks));
}

extern "C" void kernel_launch(void* const* d_in, const int* in_sizes, int n_in,
                              void* d_out, int out_size) {
    const float* q     = (const float*)d_in[0];
    const float* k     = (const float*)d_in[1];
    const float* v     = (const float*)d_in[2];
    const float* beta  = (const float*)d_in[3];
    const float* gate  = (const float*)d_in[4];
    const float* state = (const float*)d_in[5];
    float* out = (float*)d_out;

    const int BH = in_sizes[3];                     // beta: B*H elements
    const int dyn_smem = NCHUNK * CHUNK_BYTES;      // 64 KB

    cudaFuncSetAttribute(deltanet_tma_kernel,
                         cudaFuncAttributeMaxDynamicSharedMemorySize, dyn_smem);

    deltanet_tma_kernel<<<BH, 128, dyn_smem>>>(q, k, v, beta, gate, state, out);
}